// round 12
// baseline (speedup 1.0000x reference)
#include <cuda_runtime.h>
#include <math.h>

#define BATCH 64
#define NGT 40
#define LCAP 14                   // max candidates per lane (region <= 441 cells)
#define WCAP (32*LCAP)            // 448 stripe entries per warp
#define FEPS 1e-7f
#define NASSIGN (BATCH*3*10)      // 1920 assign blocks (4 warps -> 40 GTs each)
#define NOBJ (BATCH*21)           // 1344 obj blocks, 1600 cells each
#define NB2 (BATCH*3)             // 192 (b,lev) merge units
#define NUNIT (BATCH*3*NGT)
#define EMAX (NGT*10)
#define NDONE (NOBJ + NB2)        // 1536 completion events before final reduce

// ---- static device scratch (zero-initialized; counters self-reset) ----
__device__ int    A_nsel[NUNIT];
__device__ float  A_biou[NUNIT];
__device__ int    A_cell[NUNIT*10];
__device__ float  g_pobj[NOBJ];
__device__ double g_ploss[NB2];
__device__ int    g_pc[NB2];
__device__ int    g_done;

// focal obj term at z=0 (fast intrinsics; must match correction in merge)
__device__ __forceinline__ float obj0(float x) {
    float e = __expf(-fabsf(x));
    float sp = fmaxf(x, 0.f) + __logf(1.f + e);
    float prob = (x >= 0.f) ? __fdividef(1.f, 1.f + e) : __fdividef(e, 1.f + e);
    return 0.75f * prob * prob * sp;
}

__device__ __forceinline__ int nearest_idx(float t, int n) {
    float f = floorf(t);
    int i = (int)f;
    if (i < 0) return 0;
    if (i >= n - 1) return n - 1;
    float d1 = t - f, d2 = (f + 1.f) - t;
    return (d2 < d1) ? i + 1 : i;
}

// pred box + iou vs gt for one cell (fast intrinsics)
__device__ __forceinline__ float cell_iou(const float* __restrict__ pb, int HW, int cell,
                                          float gx, float gy, float s,
                                          float tx1, float ty1, float tx2, float ty2, float ga) {
    float v1 = pb[HW + cell], v2 = pb[2 * HW + cell];
    float v3 = pb[3 * HW + cell], v4 = pb[4 * HW + cell];
    float pcx = (__fdividef(1.f, 1.f + __expf(-v1)) + gx) * s;
    float pcy = (__fdividef(1.f, 1.f + __expf(-v2)) + gy) * s;
    float pw = __expf(fminf(fmaxf(v3, -5.f), 5.f)) * s;
    float ph = __expf(fminf(fmaxf(v4, -5.f), 5.f)) * s;
    float px1 = pcx - pw * 0.5f, py1 = pcy - ph * 0.5f;
    float px2 = pcx + pw * 0.5f, py2 = pcy + ph * 0.5f;
    float iw = fmaxf(fminf(px2, tx2) - fmaxf(px1, tx1), 0.f);
    float ih = fmaxf(fminf(py2, ty2) - fmaxf(py1, ty1), 0.f);
    float inter = iw * ih;
    float aa = (px2 - px1) * (py2 - py1);
    return __fdividef(inter, aa + ga - inter + FEPS);
}

// assign stripes and merge arrays are temporally disjoint -> union saves smem
union SBuf {
    struct { int idx[4][WCAP]; float cst[4][WCAP]; } a;
    struct { float tgm[NGT * 7]; int nsel[NGT]; int off[NGT + 1];
             int cell[EMAX]; int gg[EMAX]; float iou[EMAX]; } m;
};

__global__ __launch_bounds__(128, 12) void k_all(const float* __restrict__ p0,
                                                 const float* __restrict__ p1,
                                                 const float* __restrict__ p2,
                                                 const float* __restrict__ tg,
                                                 float* __restrict__ out) {
    __shared__ SBuf  S;
    __shared__ int   s_sel[4][10];
    __shared__ float s_od[4], s_bs[4], s_fs[4];
    __shared__ int   s_np[4];
    __shared__ double shd[4];
    __shared__ int   s_flag;

    int tid = threadIdx.x;

    if (blockIdx.x >= NASSIGN) {
        // ============ obj role: z=0 focal loss over one contiguous 1600-cell chunk ============
        int obid = blockIdx.x - NASSIGN;
        int b = obid / 21, c21 = obid % 21;
        const float* pr; int hw, base; float invhw;
        if (c21 < 16)      { pr = p0; hw = 25600; base = c21 * 1600;        invhw = 1.f / 25600.f; }
        else if (c21 < 20) { pr = p1; hw = 6400;  base = (c21 - 16) * 1600; invhw = 1.f / 6400.f; }
        else               { pr = p2; hw = 1600;  base = 0;                 invhw = 1.f / 1600.f; }
        const float* pb = pr + (size_t)b * 7 * hw + base;
        float acc = 0.f;
        #pragma unroll 4
        for (int j = tid; j < 1600; j += 128) acc += obj0(pb[j]);
        acc *= invhw;
        for (int o = 16; o; o >>= 1) acc += __shfl_down_sync(0xffffffffu, acc, o);
        if ((tid & 31) == 0) s_od[tid >> 5] = acc;
        __syncthreads();
        if (tid == 0) {
            g_pobj[obid] = s_od[0] + s_od[1] + s_od[2] + s_od[3];
            __threadfence();
            s_flag = (atomicAdd(&g_done, 1) == NDONE - 1);
        }
        __syncthreads();
        if (!s_flag) return;
        goto final_reduce;
    }

    {
        // ============ assign role: one warp per GT, lane-private stripes (no ballot) ============
        int bid = blockIdx.x;
        int b = bid / 30, rr = bid % 30;
        int lev = rr / 10, chunk = rr % 10;
        int wid = tid >> 5, lane = tid & 31;
        int g = chunk * 4 + wid;
        int mb = b * 3 + lev;                 // merge unit id
        int u = mb * NGT + g;

        const float* tb = tg + (b * NGT + g) * 7;
        float cls = tb[0], cx = tb[1], cy = tb[2], w = tb[3], h = tb[4];
        float size = fmaxf(w, h) * 1280.f;
        bool valid = (cls == 0.f);
        int HW, W; float s; const float* pr;
        if (lev == 0)      { HW = 25600; W = 160; s = 0.00625f; pr = p0; valid = valid && (size < 128.f); }
        else if (lev == 1) { HW = 6400;  W = 80;  s = 0.0125f;  pr = p1; valid = valid && (size >= 48.f && size < 288.f); }
        else               { HW = 1600;  W = 40;  s = 0.025f;   pr = p2; valid = valid && (size >= 128.f); }

        if (!valid) {
            if (lane == 0) A_nsel[u] = 0;
        } else {
            const float* pb = pr + (size_t)b * 7 * HW;
            float inv_s = 1.f / s;
            float cxg = cx * inv_s, cyg = cy * inv_s;
            float tx1 = cx - w * 0.5f, ty1 = cy - h * 0.5f;
            float tx2 = cx + w * 0.5f, ty2 = cy + h * 0.5f;
            float bxlo = tx1 * inv_s, bxhi = tx2 * inv_s, bylo = ty1 * inv_s, byhi = ty2 * inv_s;
            float ga = (tx2 - tx1) * (ty2 - ty1);

            int x0 = (int)floorf(fminf(cxg - 2.5f, bxlo)); if (x0 < 0) x0 = 0;
            int x1 = (int)ceilf (fmaxf(cxg + 2.5f, bxhi)); if (x1 > W - 1) x1 = W - 1;
            int y0 = (int)floorf(fminf(cyg - 2.5f, bylo)); if (y0 < 0) y0 = 0;
            int y1 = (int)ceilf (fmaxf(cyg + 2.5f, byhi)); if (y1 > W - 1) y1 = W - 1;
            int rw = x1 - x0 + 1, rh = y1 - y0 + 1;
            int rn = (rw > 0 && rh > 0) ? rw * rh : 0;
            float inv_rw = __fdividef(1.f, (float)rw);

            int basee = lane * LCAP;
            float lsum = 0.f;
            int myn = 0;
            // independent iterations: loads pipeline across the whole region
            #pragma unroll 2
            for (int i = lane; i < rn; i += 32) {
                int row = (int)(((float)i + 0.5f) * inv_rw);   // exact for small rw
                int gyi = y0 + row, gxi = x0 + (i - row * rw);
                float gx = (float)gxi, gy = (float)gyi;
                int cell = gyi * W + gxi;
                float v0 = pb[cell];
                float v1 = pb[HW + cell], v2 = pb[2 * HW + cell];
                float v3 = pb[3 * HW + cell], v4 = pb[4 * HW + cell];
                bool inc = (fabsf(gx - cxg) < 2.5f) && (fabsf(gy - cyg) < 2.5f);
                bool inb = (gx >= bxlo) && (gx < bxhi) && (gy >= bylo) && (gy < byhi);
                if (inc || inb) {
                    float pcx = (__fdividef(1.f, 1.f + __expf(-v1)) + gx) * s;
                    float pcy = (__fdividef(1.f, 1.f + __expf(-v2)) + gy) * s;
                    float pw = __expf(fminf(fmaxf(v3, -5.f), 5.f)) * s;
                    float ph = __expf(fminf(fmaxf(v4, -5.f), 5.f)) * s;
                    float px1 = pcx - pw * 0.5f, py1 = pcy - ph * 0.5f;
                    float px2 = pcx + pw * 0.5f, py2 = pcy + ph * 0.5f;
                    float iw = fmaxf(fminf(px2, tx2) - fmaxf(px1, tx1), 0.f);
                    float ih = fmaxf(fminf(py2, ty2) - fmaxf(py1, ty1), 0.f);
                    float inter = iw * ih;
                    float aa = (px2 - px1) * (py2 - py1);
                    float iou = __fdividef(inter, aa + ga - inter + FEPS);
                    float t = -v0;
                    float cc = fmaxf(t, 0.f) + __logf(1.f + __expf(-fabsf(t))) - 3.f * __logf(iou + FEPS);
                    if (myn < LCAP) {
                        S.a.idx[wid][basee + myn] = cell;
                        S.a.cst[wid][basee + myn] = cc;
                    }
                    myn++;
                    lsum += iou;
                }
            }
            // pad unused stripe slots
            for (int j = myn; j < LCAP; ++j) {
                S.a.cst[wid][basee + j] = 3.4e38f;
                S.a.idx[wid][basee + j] = 0x7fffffff;
            }
            int ncand = myn;
            for (int o = 16; o; o >>= 1) {
                lsum  += __shfl_xor_sync(0xffffffffu, lsum, o);
                ncand += __shfl_xor_sync(0xffffffffu, ncand, o);
            }
            __syncwarp();

            if (ncand == 0) {
                if (lane == 0) {
                    int nx = nearest_idx(cxg, W), ny = nearest_idx(cyg, W);
                    int cell = ny * W + nx;
                    A_nsel[u] = 1;
                    A_biou[u] = cell_iou(pb, HW, cell, (float)nx, (float)ny, s, tx1, ty1, tx2, ty2, ga);
                    A_cell[u * 10] = cell;
                }
            } else {
                int np = (int)floorf(lsum);
                int mx = ncand < 10 ? ncand : 10;
                if (np < 1) np = 1;
                if (np > mx) np = mx;

                for (int k = 0; k < np; ++k) {
                    float mc = 3.4e38f; int mi = 0x7fffffff; int me = -1;
                    #pragma unroll
                    for (int j = 0; j < LCAP; ++j) {
                        float cc = S.a.cst[wid][basee + j];
                        int ci = S.a.idx[wid][basee + j];
                        if (cc < mc || (cc == mc && ci < mi)) { mc = cc; mi = ci; me = basee + j; }
                    }
                    float lmc = mc; int lmi = mi;       // local best before reduce
                    for (int o = 16; o; o >>= 1) {
                        float oc = __shfl_xor_sync(0xffffffffu, mc, o);
                        int   oi = __shfl_xor_sync(0xffffffffu, mi, o);
                        if (oc < mc || (oc == mc && oi < mi)) { mc = oc; mi = oi; }
                    }
                    // stripe owner of the winning entry marks it consumed
                    if (me >= 0 && lmi == mi && lmc == mc) S.a.cst[wid][me] = 3.4e38f;
                    if (lane == 0) s_sel[wid][k] = mi;
                    __syncwarp();
                }
                if (lane == 0) {
                    A_nsel[u] = np;
                    int c0 = s_sel[wid][0];
                    A_biou[u] = cell_iou(pb, HW, c0, (float)(c0 % W), (float)(c0 / W), s, tx1, ty1, tx2, ty2, ga);
                    for (int k = 0; k < np; ++k) A_cell[u * 10 + k] = s_sel[wid][k];
                }
            }
        }
        __threadfence();       // make this thread's global writes visible pre-counter
        __syncthreads();
        if (tid == 0) s_flag = (atomicAdd(&g_pc[mb], 1) == 9);
        __syncthreads();
        if (!s_flag) return;

        // ============ merge role: last-arriving block of this (b,lev) ============
        __threadfence();   // acquire: counter observed -> scratch reads see all writes
        {
            const float* pbm = pr + (size_t)b * 7 * HW;
            for (int i = tid; i < NGT * 7; i += 128) S.m.tgm[i] = tg[b * NGT * 7 + i];
            if (tid < NGT) S.m.nsel[tid] = __ldcg(&A_nsel[mb * NGT + tid]);
            __syncthreads();
            if (tid == 0) {
                int o = 0;
                for (int gg2 = 0; gg2 < NGT; ++gg2) { S.m.off[gg2] = o; o += S.m.nsel[gg2]; }
                S.m.off[NGT] = o;
            }
            __syncthreads();
            int tcnt = S.m.off[NGT];

            for (int t = tid; t < NGT * 10; t += 128) {
                int gg2 = t / 10, k = t % 10;
                int ns = S.m.off[gg2 + 1] - S.m.off[gg2];
                if (k < ns) {
                    int uu = mb * NGT + gg2;
                    int e = S.m.off[gg2] + k;
                    S.m.cell[e] = __ldcg(&A_cell[uu * 10 + k]);
                    S.m.gg[e] = gg2;
                    S.m.iou[e] = __ldcg(&A_biou[uu]);
                }
            }
            __syncthreads();

            float od = 0.f, bs = 0.f, fs = 0.f;
            int np = 0;
            for (int e = tid; e < tcnt; e += 128) {
                int c = S.m.cell[e], ge = S.m.gg[e];
                float z = S.m.iou[e];
                bool win = true;
                for (int e2 = 0; e2 < tcnt; ++e2) {
                    if (e2 == e) continue;
                    if (S.m.cell[e2] == c) {
                        z = fmaxf(z, S.m.iou[e2]);
                        if (S.m.gg[e2] > ge) win = false;
                    }
                }
                if (!win) continue;
                np++;

                // obj correction: focal(x,z) - focal(x,0) (identical formula to obj0)
                float x = pbm[c];
                float eab = __expf(-fabsf(x));
                float l1p = __logf(1.f + eab);
                float prob = (x >= 0.f) ? __fdividef(1.f, 1.f + eab) : __fdividef(eab, 1.f + eab);
                float ce0 = fmaxf(x, 0.f) + l1p;
                float t0 = 0.75f * prob * prob * ce0;
                float ce = ce0 - x * z;
                float pt = prob * z + (1.f - prob) * (1.f - z);
                float at = 0.25f * z + 0.75f * (1.f - z);
                float om = 1.f - pt;
                od += at * om * om * ce - t0;

                float cxm = S.m.tgm[ge * 7 + 1], cym = S.m.tgm[ge * 7 + 2];
                float wm = S.m.tgm[ge * 7 + 3], hm = S.m.tgm[ge * 7 + 4];
                float fx = S.m.tgm[ge * 7 + 5], fy = S.m.tgm[ge * 7 + 6];
                float cxg2 = cxm / s, cyg2 = cym / s;
                int gxi = c % W, gyi = c / W;
                float gx = (float)gxi, gy = (float)gyi;
                float tb0 = cxg2 - gx, tb1 = cyg2 - gy;
                float lw = logf(wm / s + FEPS), lh = logf(hm / s + FEPS);

                float v1 = pbm[HW + c], v2 = pbm[2 * HW + c], v3 = pbm[3 * HW + c], v4 = pbm[4 * HW + c];
                float pcx = (1.f / (1.f + expf(-v1)) + gx) * s;
                float pcy = (1.f / (1.f + expf(-v2)) + gy) * s;
                float pw = expf(fminf(fmaxf(v3, -5.f), 5.f)) * s;
                float ph = expf(fminf(fmaxf(v4, -5.f), 5.f)) * s;
                float tcx = (tb0 + gx) * s, tcy = (tb1 + gy) * s;
                float tw = expf(lw) * s, th = expf(lh) * s;
                float px1 = pcx - pw * 0.5f, py1 = pcy - ph * 0.5f;
                float px2 = pcx + pw * 0.5f, py2 = pcy + ph * 0.5f;
                float qx1 = tcx - tw * 0.5f, qy1 = tcy - th * 0.5f;
                float qx2 = tcx + tw * 0.5f, qy2 = tcy + th * 0.5f;
                float iw = fmaxf(fminf(px2, qx2) - fmaxf(px1, qx1), 0.f);
                float ih = fmaxf(fminf(py2, qy2) - fmaxf(py1, qy1), 0.f);
                float inter = iw * ih;
                float uni = pw * ph + tw * th - inter + FEPS;
                float iou = inter / uni;
                float rho2 = (pcx - tcx) * (pcx - tcx) + (pcy - tcy) * (pcy - tcy);
                float cw2 = fmaxf(px2, qx2) - fminf(px1, qx1);
                float ch2 = fmaxf(py2, qy2) - fminf(py1, qy1);
                float c2 = cw2 * cw2 + ch2 * ch2 + FEPS;
                float dv = atanf(tw / (th + FEPS)) - atanf(pw / (ph + FEPS));
                float v = 0.405284734569351f * dv * dv;   // 4/pi^2
                float alpha = v / (1.f - iou + v + FEPS);
                float ciou = iou - rho2 / c2 - alpha * v;
                bs += 1.f - ciou;

                float pf0 = 1.f / (1.f + expf(-pbm[5 * HW + c]));
                float pf1 = 1.f / (1.f + expf(-pbm[6 * HW + c]));
                float d0 = fabsf(pf0 - fx);
                float d1 = fabsf(pf1 - fy);
                fs += ((d0 < 1.f) ? 0.5f * d0 * d0 : d0 - 0.5f)
                    + ((d1 < 1.f) ? 0.5f * d1 * d1 : d1 - 0.5f);
            }
            for (int o = 16; o; o >>= 1) {
                od += __shfl_down_sync(0xffffffffu, od, o);
                bs += __shfl_down_sync(0xffffffffu, bs, o);
                fs += __shfl_down_sync(0xffffffffu, fs, o);
                np += __shfl_down_sync(0xffffffffu, np, o);
            }
            if ((tid & 31) == 0) { int w2 = tid >> 5; s_od[w2] = od; s_bs[w2] = bs; s_fs[w2] = fs; s_np[w2] = np; }
            __syncthreads();
            if (tid == 0) {
                float O = s_od[0] + s_od[1] + s_od[2] + s_od[3];
                float Bx = s_bs[0] + s_bs[1] + s_bs[2] + s_bs[3];
                float F = s_fs[0] + s_fs[1] + s_fs[2] + s_fs[3];
                int npos = s_np[0] + s_np[1] + s_np[2] + s_np[3];
                double den = (npos > 0) ? (double)npos : 1.0;
                g_ploss[mb] = (double)O / (double)HW + (5.0 * (double)Bx + (double)F) / den;
                __threadfence();
                s_flag = (atomicAdd(&g_done, 1) == NDONE - 1);
            }
            __syncthreads();
            if (!s_flag) return;
        }
    }

final_reduce:
    // ============ final role: last completion event reduces everything ============
    {
        __threadfence();
        double a = 0.0;
        for (int i = tid; i < NOBJ; i += 128) a += (double)__ldcg(&g_pobj[i]);
        for (int i = tid; i < NB2; i += 128) a += __ldcg(&g_ploss[i]);
        for (int o = 16; o; o >>= 1) a += __shfl_down_sync(0xffffffffu, a, o);
        if ((tid & 31) == 0) shd[tid >> 5] = a;
        __syncthreads();
        if (tid == 0) out[0] = (float)((shd[0] + shd[1] + shd[2] + shd[3]) / 64.0);
        // reset counters for next graph replay (launches are stream-serialized)
        for (int i = tid; i < NB2; i += 128) g_pc[i] = 0;
        if (tid == 0) g_done = 0;
    }
}

extern "C" void kernel_launch(void* const* d_in, const int* in_sizes, int n_in,
                              void* d_out, int out_size) {
    const float* p0 = (const float*)d_in[0];
    const float* p1 = (const float*)d_in[1];
    const float* p2 = (const float*)d_in[2];
    const float* tg = (const float*)d_in[3];
    k_all<<<NASSIGN + NOBJ, 128>>>(p0, p1, p2, tg, (float*)d_out);
}

// round 16
// speedup vs baseline: 1.0322x; 1.0322x over previous
#include <cuda_runtime.h>
#include <math.h>

#define BATCH 64
#define NGT 40
#define LCAP 14                   // max candidates per lane (region <= 441 cells)
#define WCAP (32*LCAP)            // 448 stripe entries per warp
#define FEPS 1e-7f
#define NASSIGN (BATCH*3*10)      // 1920 assign blocks (4 warps -> 40 GTs each)
#define NOBJ (BATCH*21)           // 1344 obj blocks, 1600 cells each
#define NB2 (BATCH*3)             // 192 (b,lev) merge units
#define NUNIT (BATCH*3*NGT)
#define EMAX (NGT*10)
#define NDONE (NOBJ + NB2)        // 1536 completion events before final reduce

// ---- static device scratch (zero-initialized; counters self-reset) ----
__device__ int    A_nsel[NUNIT];
__device__ float  A_biou[NUNIT];
__device__ int    A_cell[NUNIT*10];
__device__ float  g_pobj[NOBJ];
__device__ double g_ploss[NB2];
__device__ int    g_pc[NB2];
__device__ int    g_done;

// focal obj term at z=0 (fast intrinsics; must match correction in merge)
__device__ __forceinline__ float obj0(float x) {
    float e = __expf(-fabsf(x));
    float sp = fmaxf(x, 0.f) + __logf(1.f + e);
    float prob = (x >= 0.f) ? __fdividef(1.f, 1.f + e) : __fdividef(e, 1.f + e);
    return 0.75f * prob * prob * sp;
}

__device__ __forceinline__ int nearest_idx(float t, int n) {
    float f = floorf(t);
    int i = (int)f;
    if (i < 0) return 0;
    if (i >= n - 1) return n - 1;
    float d1 = t - f, d2 = (f + 1.f) - t;
    return (d2 < d1) ? i + 1 : i;
}

// pred box + iou vs gt for one cell (fast intrinsics)
__device__ __forceinline__ float cell_iou(const float* __restrict__ pb, int HW, int cell,
                                          float gx, float gy, float s,
                                          float tx1, float ty1, float tx2, float ty2, float ga) {
    float v1 = pb[HW + cell], v2 = pb[2 * HW + cell];
    float v3 = pb[3 * HW + cell], v4 = pb[4 * HW + cell];
    float pcx = (__fdividef(1.f, 1.f + __expf(-v1)) + gx) * s;
    float pcy = (__fdividef(1.f, 1.f + __expf(-v2)) + gy) * s;
    float pw = __expf(fminf(fmaxf(v3, -5.f), 5.f)) * s;
    float ph = __expf(fminf(fmaxf(v4, -5.f), 5.f)) * s;
    float px1 = pcx - pw * 0.5f, py1 = pcy - ph * 0.5f;
    float px2 = pcx + pw * 0.5f, py2 = pcy + ph * 0.5f;
    float iw = fmaxf(fminf(px2, tx2) - fmaxf(px1, tx1), 0.f);
    float ih = fmaxf(fminf(py2, ty2) - fmaxf(py1, ty1), 0.f);
    float inter = iw * ih;
    float aa = (px2 - px1) * (py2 - py1);
    return __fdividef(inter, aa + ga - inter + FEPS);
}

// assign stripes and merge arrays are temporally disjoint -> union saves smem
union SBuf {
    struct { int idx[4][WCAP]; float cst[4][WCAP]; } a;
    struct { float tgm[NGT * 7]; int nsel[NGT]; int off[NGT + 1];
             int cell[EMAX]; int gg[EMAX]; float iou[EMAX]; } m;
};

__global__ __launch_bounds__(128) void k_all(const float* __restrict__ p0,
                                             const float* __restrict__ p1,
                                             const float* __restrict__ p2,
                                             const float* __restrict__ tg,
                                             float* __restrict__ out) {
    __shared__ SBuf  S;
    __shared__ int   s_sel[4][10];
    __shared__ float s_od[4], s_bs[4], s_fs[4];
    __shared__ int   s_np[4];
    __shared__ double shd[4];
    __shared__ int   s_flag;

    int tid = threadIdx.x;

    if (blockIdx.x >= NASSIGN) {
        // ============ obj role: z=0 focal loss over one contiguous 1600-cell chunk ============
        int obid = blockIdx.x - NASSIGN;
        int b = obid / 21, c21 = obid % 21;
        const float* pr; int hw, base; float invhw;
        if (c21 < 16)      { pr = p0; hw = 25600; base = c21 * 1600;        invhw = 1.f / 25600.f; }
        else if (c21 < 20) { pr = p1; hw = 6400;  base = (c21 - 16) * 1600; invhw = 1.f / 6400.f; }
        else               { pr = p2; hw = 1600;  base = 0;                 invhw = 1.f / 1600.f; }
        // 16B-aligned: 7*hw*4 and base*4 are multiples of 16
        const float4* pb4 = reinterpret_cast<const float4*>(pr + (size_t)b * 7 * hw + base);
        float acc = 0.f;
        #pragma unroll 2
        for (int j = tid; j < 400; j += 128) {
            float4 v = pb4[j];
            acc += obj0(v.x) + obj0(v.y) + obj0(v.z) + obj0(v.w);
        }
        acc *= invhw;
        for (int o = 16; o; o >>= 1) acc += __shfl_down_sync(0xffffffffu, acc, o);
        if ((tid & 31) == 0) s_od[tid >> 5] = acc;
        __syncthreads();
        if (tid == 0) {
            g_pobj[obid] = s_od[0] + s_od[1] + s_od[2] + s_od[3];
            __threadfence();
            s_flag = (atomicAdd(&g_done, 1) == NDONE - 1);
        }
        __syncthreads();
        if (!s_flag) return;
        goto final_reduce;
    }

    {
        // ============ assign role: one warp per GT, lane-private stripes (no ballot) ============
        int bid = blockIdx.x;
        int b = bid / 30, rr = bid % 30;
        int lev = rr / 10, chunk = rr % 10;
        int wid = tid >> 5, lane = tid & 31;
        int g = chunk * 4 + wid;
        int mb = b * 3 + lev;                 // merge unit id
        int u = mb * NGT + g;

        const float* tb = tg + (b * NGT + g) * 7;
        float cls = tb[0], cx = tb[1], cy = tb[2], w = tb[3], h = tb[4];
        float size = fmaxf(w, h) * 1280.f;
        bool valid = (cls == 0.f);
        int HW, W; float s; const float* pr;
        if (lev == 0)      { HW = 25600; W = 160; s = 0.00625f; pr = p0; valid = valid && (size < 128.f); }
        else if (lev == 1) { HW = 6400;  W = 80;  s = 0.0125f;  pr = p1; valid = valid && (size >= 48.f && size < 288.f); }
        else               { HW = 1600;  W = 40;  s = 0.025f;   pr = p2; valid = valid && (size >= 128.f); }

        if (!valid) {
            if (lane == 0) A_nsel[u] = 0;
        } else {
            const float* pb = pr + (size_t)b * 7 * HW;
            float inv_s = 1.f / s;
            float cxg = cx * inv_s, cyg = cy * inv_s;
            float tx1 = cx - w * 0.5f, ty1 = cy - h * 0.5f;
            float tx2 = cx + w * 0.5f, ty2 = cy + h * 0.5f;
            float bxlo = tx1 * inv_s, bxhi = tx2 * inv_s, bylo = ty1 * inv_s, byhi = ty2 * inv_s;
            float ga = (tx2 - tx1) * (ty2 - ty1);

            int x0 = (int)floorf(fminf(cxg - 2.5f, bxlo)); if (x0 < 0) x0 = 0;
            int x1 = (int)ceilf (fmaxf(cxg + 2.5f, bxhi)); if (x1 > W - 1) x1 = W - 1;
            int y0 = (int)floorf(fminf(cyg - 2.5f, bylo)); if (y0 < 0) y0 = 0;
            int y1 = (int)ceilf (fmaxf(cyg + 2.5f, byhi)); if (y1 > W - 1) y1 = W - 1;
            int rw = x1 - x0 + 1, rh = y1 - y0 + 1;
            int rn = (rw > 0 && rh > 0) ? rw * rh : 0;
            float inv_rw = __fdividef(1.f, (float)rw);

            int basee = lane * LCAP;
            float lsum = 0.f;
            int myn = 0;
            // independent iterations: loads pipeline across the whole region
            for (int i = lane; i < rn; i += 32) {
                int row = (int)(((float)i + 0.5f) * inv_rw);   // exact for small rw
                int gyi = y0 + row, gxi = x0 + (i - row * rw);
                float gx = (float)gxi, gy = (float)gyi;
                int cell = gyi * W + gxi;
                float v0 = pb[cell];
                float v1 = pb[HW + cell], v2 = pb[2 * HW + cell];
                float v3 = pb[3 * HW + cell], v4 = pb[4 * HW + cell];
                bool inc = (fabsf(gx - cxg) < 2.5f) && (fabsf(gy - cyg) < 2.5f);
                bool inb = (gx >= bxlo) && (gx < bxhi) && (gy >= bylo) && (gy < byhi);
                if (inc || inb) {
                    float pcx = (__fdividef(1.f, 1.f + __expf(-v1)) + gx) * s;
                    float pcy = (__fdividef(1.f, 1.f + __expf(-v2)) + gy) * s;
                    float pw = __expf(fminf(fmaxf(v3, -5.f), 5.f)) * s;
                    float ph = __expf(fminf(fmaxf(v4, -5.f), 5.f)) * s;
                    float px1 = pcx - pw * 0.5f, py1 = pcy - ph * 0.5f;
                    float px2 = pcx + pw * 0.5f, py2 = pcy + ph * 0.5f;
                    float iw = fmaxf(fminf(px2, tx2) - fmaxf(px1, tx1), 0.f);
                    float ih = fmaxf(fminf(py2, ty2) - fmaxf(py1, ty1), 0.f);
                    float inter = iw * ih;
                    float aa = (px2 - px1) * (py2 - py1);
                    float iou = __fdividef(inter, aa + ga - inter + FEPS);
                    float t = -v0;
                    float cc = fmaxf(t, 0.f) + __logf(1.f + __expf(-fabsf(t))) - 3.f * __logf(iou + FEPS);
                    if (myn < LCAP) {
                        S.a.idx[wid][basee + myn] = cell;
                        S.a.cst[wid][basee + myn] = cc;
                    }
                    myn++;
                    lsum += iou;
                }
            }
            // pad unused stripe slots
            for (int j = myn; j < LCAP; ++j) {
                S.a.cst[wid][basee + j] = 3.4e38f;
                S.a.idx[wid][basee + j] = 0x7fffffff;
            }
            int ncand = myn;
            for (int o = 16; o; o >>= 1) {
                lsum  += __shfl_xor_sync(0xffffffffu, lsum, o);
                ncand += __shfl_xor_sync(0xffffffffu, ncand, o);
            }
            __syncwarp();

            if (ncand == 0) {
                if (lane == 0) {
                    int nx = nearest_idx(cxg, W), ny = nearest_idx(cyg, W);
                    int cell = ny * W + nx;
                    A_nsel[u] = 1;
                    A_biou[u] = cell_iou(pb, HW, cell, (float)nx, (float)ny, s, tx1, ty1, tx2, ty2, ga);
                    A_cell[u * 10] = cell;
                }
            } else {
                int np = (int)floorf(lsum);
                int mx = ncand < 10 ? ncand : 10;
                if (np < 1) np = 1;
                if (np > mx) np = mx;

                for (int k = 0; k < np; ++k) {
                    float mc = 3.4e38f; int mi = 0x7fffffff; int me = -1;
                    #pragma unroll
                    for (int j = 0; j < LCAP; ++j) {
                        float cc = S.a.cst[wid][basee + j];
                        int ci = S.a.idx[wid][basee + j];
                        if (cc < mc || (cc == mc && ci < mi)) { mc = cc; mi = ci; me = basee + j; }
                    }
                    float lmc = mc; int lmi = mi;       // local best before reduce
                    for (int o = 16; o; o >>= 1) {
                        float oc = __shfl_xor_sync(0xffffffffu, mc, o);
                        int   oi = __shfl_xor_sync(0xffffffffu, mi, o);
                        if (oc < mc || (oc == mc && oi < mi)) { mc = oc; mi = oi; }
                    }
                    // stripe owner of the winning entry marks it consumed
                    if (me >= 0 && lmi == mi && lmc == mc) S.a.cst[wid][me] = 3.4e38f;
                    if (lane == 0) s_sel[wid][k] = mi;
                    __syncwarp();
                }
                if (lane == 0) {
                    A_nsel[u] = np;
                    int c0 = s_sel[wid][0];
                    A_biou[u] = cell_iou(pb, HW, c0, (float)(c0 % W), (float)(c0 / W), s, tx1, ty1, tx2, ty2, ga);
                    for (int k = 0; k < np; ++k) A_cell[u * 10 + k] = s_sel[wid][k];
                }
            }
        }
        __threadfence();       // make this thread's global writes visible pre-counter
        __syncthreads();
        if (tid == 0) s_flag = (atomicAdd(&g_pc[mb], 1) == 9);
        __syncthreads();
        if (!s_flag) return;

        // ============ merge role: last-arriving block of this (b,lev) ============
        __threadfence();   // acquire: counter observed -> scratch reads see all writes
        {
            const float* pbm = pr + (size_t)b * 7 * HW;
            for (int i = tid; i < NGT * 7; i += 128) S.m.tgm[i] = tg[b * NGT * 7 + i];
            if (tid < NGT) S.m.nsel[tid] = __ldcg(&A_nsel[mb * NGT + tid]);
            __syncthreads();
            if (tid == 0) {
                int o = 0;
                for (int gg2 = 0; gg2 < NGT; ++gg2) { S.m.off[gg2] = o; o += S.m.nsel[gg2]; }
                S.m.off[NGT] = o;
            }
            __syncthreads();
            int tcnt = S.m.off[NGT];

            for (int t = tid; t < NGT * 10; t += 128) {
                int gg2 = t / 10, k = t % 10;
                int ns = S.m.off[gg2 + 1] - S.m.off[gg2];
                if (k < ns) {
                    int uu = mb * NGT + gg2;
                    int e = S.m.off[gg2] + k;
                    S.m.cell[e] = __ldcg(&A_cell[uu * 10 + k]);
                    S.m.gg[e] = gg2;
                    S.m.iou[e] = __ldcg(&A_biou[uu]);
                }
            }
            __syncthreads();

            float od = 0.f, bs = 0.f, fs = 0.f;
            int np = 0;
            for (int e = tid; e < tcnt; e += 128) {
                int c = S.m.cell[e], ge = S.m.gg[e];
                float z = S.m.iou[e];
                bool win = true;
                for (int e2 = 0; e2 < tcnt; ++e2) {
                    if (e2 == e) continue;
                    if (S.m.cell[e2] == c) {
                        z = fmaxf(z, S.m.iou[e2]);
                        if (S.m.gg[e2] > ge) win = false;
                    }
                }
                if (!win) continue;
                np++;

                // obj correction: focal(x,z) - focal(x,0) (identical formula to obj0)
                float x = pbm[c];
                float eab = __expf(-fabsf(x));
                float l1p = __logf(1.f + eab);
                float prob = (x >= 0.f) ? __fdividef(1.f, 1.f + eab) : __fdividef(eab, 1.f + eab);
                float ce0 = fmaxf(x, 0.f) + l1p;
                float t0 = 0.75f * prob * prob * ce0;
                float ce = ce0 - x * z;
                float pt = prob * z + (1.f - prob) * (1.f - z);
                float at = 0.25f * z + 0.75f * (1.f - z);
                float om = 1.f - pt;
                od += at * om * om * ce - t0;

                float cxm = S.m.tgm[ge * 7 + 1], cym = S.m.tgm[ge * 7 + 2];
                float wm = S.m.tgm[ge * 7 + 3], hm = S.m.tgm[ge * 7 + 4];
                float fx = S.m.tgm[ge * 7 + 5], fy = S.m.tgm[ge * 7 + 6];
                float cxg2 = cxm / s, cyg2 = cym / s;
                int gxi = c % W, gyi = c / W;
                float gx = (float)gxi, gy = (float)gyi;
                float tb0 = cxg2 - gx, tb1 = cyg2 - gy;
                float lw = __logf(wm / s + FEPS), lh = __logf(hm / s + FEPS);

                float v1 = pbm[HW + c], v2 = pbm[2 * HW + c], v3 = pbm[3 * HW + c], v4 = pbm[4 * HW + c];
                float pcx = (__fdividef(1.f, 1.f + __expf(-v1)) + gx) * s;
                float pcy = (__fdividef(1.f, 1.f + __expf(-v2)) + gy) * s;
                float pw = __expf(fminf(fmaxf(v3, -5.f), 5.f)) * s;
                float ph = __expf(fminf(fmaxf(v4, -5.f), 5.f)) * s;
                float tcx = (tb0 + gx) * s, tcy = (tb1 + gy) * s;
                float tw = __expf(lw) * s, th = __expf(lh) * s;
                float px1 = pcx - pw * 0.5f, py1 = pcy - ph * 0.5f;
                float px2 = pcx + pw * 0.5f, py2 = pcy + ph * 0.5f;
                float qx1 = tcx - tw * 0.5f, qy1 = tcy - th * 0.5f;
                float qx2 = tcx + tw * 0.5f, qy2 = tcy + th * 0.5f;
                float iw = fmaxf(fminf(px2, qx2) - fmaxf(px1, qx1), 0.f);
                float ih = fmaxf(fminf(py2, qy2) - fmaxf(py1, qy1), 0.f);
                float inter = iw * ih;
                float uni = pw * ph + tw * th - inter + FEPS;
                float iou = __fdividef(inter, uni);
                float rho2 = (pcx - tcx) * (pcx - tcx) + (pcy - tcy) * (pcy - tcy);
                float cw2 = fmaxf(px2, qx2) - fminf(px1, qx1);
                float ch2 = fmaxf(py2, qy2) - fminf(py1, qy1);
                float c2 = cw2 * cw2 + ch2 * ch2 + FEPS;
                float dv = atanf(__fdividef(tw, th + FEPS)) - atanf(__fdividef(pw, ph + FEPS));
                float v = 0.405284734569351f * dv * dv;   // 4/pi^2
                float alpha = __fdividef(v, 1.f - iou + v + FEPS);
                float ciou = iou - __fdividef(rho2, c2) - alpha * v;
                bs += 1.f - ciou;

                float pf0 = __fdividef(1.f, 1.f + __expf(-pbm[5 * HW + c]));
                float pf1 = __fdividef(1.f, 1.f + __expf(-pbm[6 * HW + c]));
                float d0 = fabsf(pf0 - fx);
                float d1 = fabsf(pf1 - fy);
                fs += ((d0 < 1.f) ? 0.5f * d0 * d0 : d0 - 0.5f)
                    + ((d1 < 1.f) ? 0.5f * d1 * d1 : d1 - 0.5f);
            }
            for (int o = 16; o; o >>= 1) {
                od += __shfl_down_sync(0xffffffffu, od, o);
                bs += __shfl_down_sync(0xffffffffu, bs, o);
                fs += __shfl_down_sync(0xffffffffu, fs, o);
                np += __shfl_down_sync(0xffffffffu, np, o);
            }
            if ((tid & 31) == 0) { int w2 = tid >> 5; s_od[w2] = od; s_bs[w2] = bs; s_fs[w2] = fs; s_np[w2] = np; }
            __syncthreads();
            if (tid == 0) {
                float O = s_od[0] + s_od[1] + s_od[2] + s_od[3];
                float Bx = s_bs[0] + s_bs[1] + s_bs[2] + s_bs[3];
                float F = s_fs[0] + s_fs[1] + s_fs[2] + s_fs[3];
                int npos = s_np[0] + s_np[1] + s_np[2] + s_np[3];
                double den = (npos > 0) ? (double)npos : 1.0;
                g_ploss[mb] = (double)O / (double)HW + (5.0 * (double)Bx + (double)F) / den;
                __threadfence();
                s_flag = (atomicAdd(&g_done, 1) == NDONE - 1);
            }
            __syncthreads();
            if (!s_flag) return;
        }
    }

final_reduce:
    // ============ final role: last completion event reduces everything ============
    {
        __threadfence();
        double a = 0.0;
        for (int i = tid; i < NOBJ; i += 128) a += (double)__ldcg(&g_pobj[i]);
        for (int i = tid; i < NB2; i += 128) a += __ldcg(&g_ploss[i]);
        for (int o = 16; o; o >>= 1) a += __shfl_down_sync(0xffffffffu, a, o);
        if ((tid & 31) == 0) shd[tid >> 5] = a;
        __syncthreads();
        if (tid == 0) out[0] = (float)((shd[0] + shd[1] + shd[2] + shd[3]) / 64.0);
        // reset counters for next graph replay (launches are stream-serialized)
        for (int i = tid; i < NB2; i += 128) g_pc[i] = 0;
        if (tid == 0) g_done = 0;
    }
}

extern "C" void kernel_launch(void* const* d_in, const int* in_sizes, int n_in,
                              void* d_out, int out_size) {
    const float* p0 = (const float*)d_in[0];
    const float* p1 = (const float*)d_in[1];
    const float* p2 = (const float*)d_in[2];
    const float* tg = (const float*)d_in[3];
    k_all<<<NASSIGN + NOBJ, 128>>>(p0, p1, p2, tg, (float*)d_out);
}